// round 7
// baseline (speedup 1.0000x reference)
#include <cuda_runtime.h>
#include <cuda_bf16.h>

// Problem constants (fixed by the dataset)
#define NUM_NODES 50000
#define DIM       128
#define NUM_EDGES 800000

// Scratch for emb = elu(graph_embedding * weight)  -- 25.6 MB
__device__ float g_emb[(size_t)NUM_NODES * DIM];

// ---------------------------------------------------------------------------
// Kernel 1: emb = elu(x * w), float4 vectorized.
// total float4 elements = NUM_NODES * DIM / 4 = 1,600,000
// ---------------------------------------------------------------------------
__global__ void emb_kernel(const float* __restrict__ x,
                           const float* __restrict__ w) {
    int i = blockIdx.x * blockDim.x + threadIdx.x;
    const int total4 = NUM_NODES * DIM / 4;
    if (i >= total4) return;

    const int col4 = i & (DIM / 4 - 1);      // DIM/4 = 32, power of two
    float4 xv = reinterpret_cast<const float4*>(x)[i];
    float4 wv = reinterpret_cast<const float4*>(w)[col4];

    float4 r;
    float a;
    a = xv.x * wv.x; r.x = (a > 0.f) ? a : expm1f(a);
    a = xv.y * wv.y; r.y = (a > 0.f) ? a : expm1f(a);
    a = xv.z * wv.z; r.z = (a > 0.f) ? a : expm1f(a);
    a = xv.w * wv.w; r.w = (a > 0.f) ? a : expm1f(a);

    reinterpret_cast<float4*>(g_emb)[i] = r;
}

// ---------------------------------------------------------------------------
// Kernel 2: per-edge scatter. One warp per edge; lane l handles floats
// [4l, 4l+4) of the 128-wide feature row. Vector float4 atomicAdd (sm_90+)
// compiles to RED.E.ADD.F32.V4 (no return value used).
// Index arrays are int32 (JAX x64-disabled downcasts the reference's int64).
// ---------------------------------------------------------------------------
__global__ void scatter_kernel(const int* __restrict__ e_feat,
                               const int* __restrict__ src,
                               const int* __restrict__ dst,
                               float* __restrict__ out) {
    const unsigned gtid = blockIdx.x * blockDim.x + threadIdx.x;
    const unsigned edge = gtid >> 5;
    const unsigned lane = gtid & 31u;
    if (edge >= NUM_EDGES) return;

    const int s = src[edge];     // broadcast within warp via L1
    const int d = dst[edge];
    const int e = e_feat[edge];
    const float c = (e >= 0 && e < 5) ? 2.0f : 1.0f;

    float4 v = reinterpret_cast<const float4*>(g_emb + (size_t)s * DIM)[lane];
    v.x *= c; v.y *= c; v.z *= c; v.w *= c;

    float4* addr = reinterpret_cast<float4*>(out + (size_t)d * DIM) + lane;
    atomicAdd(addr, v);   // result discarded -> RED (no load-return)
}

// ---------------------------------------------------------------------------
// Launch: memset(out) -> emb -> scatter. All graph-capturable.
// Input order (metadata): graph_embedding f32, weight f32,
//                         e_feat i32, src i32, dst i32
// ---------------------------------------------------------------------------
extern "C" void kernel_launch(void* const* d_in, const int* in_sizes, int n_in,
                              void* d_out, int out_size) {
    const float* x  = (const float*)d_in[0];
    const float* w  = (const float*)d_in[1];
    const int*   ef = (const int*)d_in[2];
    const int*   sr = (const int*)d_in[3];
    const int*   ds = (const int*)d_in[4];
    float* out = (float*)d_out;

    // Output is poisoned to 0xAA -> zero it.
    cudaMemsetAsync(d_out, 0, (size_t)out_size * sizeof(float), 0);

    const int total4 = NUM_NODES * DIM / 4;          // 1,600,000
    emb_kernel<<<(total4 + 255) / 256, 256>>>(x, w);

    const long long threads = (long long)NUM_EDGES * 32; // 25.6M
    const int blocks = (int)((threads + 255) / 256);     // 100,000
    scatter_kernel<<<blocks, 256>>>(ef, sr, ds, out);
}

// round 10
// speedup vs baseline: 1.4377x; 1.4377x over previous
#include <cuda_runtime.h>
#include <cuda_bf16.h>

// Problem constants (fixed by the dataset)
#define NUM_NODES 50000
#define DIM       128
#define NUM_EDGES 800000
#define SCAN_BLOCKS ((NUM_NODES + 255) / 256)   // 196

// Device scratch (static globals are the sanctioned scratch mechanism)
__device__ float g_emb[(size_t)NUM_NODES * DIM];   // elu(x*w), 25.6 MB (L2-resident)
__device__ int   g_deg[NUM_NODES];                 // per-dst degree histogram
__device__ int   g_off[NUM_NODES + 1];             // CSR offsets
__device__ int   g_cursor[NUM_NODES];              // fill cursors
__device__ int   g_bsum[SCAN_BLOCKS];              // per-block scan totals
__device__ int   g_packed[NUM_EDGES];              // src | (coeff_flag << 16)

// ---------------------------------------------------------------------------
// Kernel 1: emb = elu(x * w), float4 vectorized. Also zeroes g_deg.
// ---------------------------------------------------------------------------
__global__ void emb_kernel(const float* __restrict__ x,
                           const float* __restrict__ w) {
    int i = blockIdx.x * blockDim.x + threadIdx.x;
    if (i < NUM_NODES) g_deg[i] = 0;               // free zeroing ride-along

    const int total4 = NUM_NODES * DIM / 4;        // 1,600,000
    if (i >= total4) return;

    const int col4 = i & (DIM / 4 - 1);            // DIM/4 = 32
    float4 xv = reinterpret_cast<const float4*>(x)[i];
    float4 wv = reinterpret_cast<const float4*>(w)[col4];

    float4 r; float a;
    a = xv.x * wv.x; r.x = (a > 0.f) ? a : expm1f(a);
    a = xv.y * wv.y; r.y = (a > 0.f) ? a : expm1f(a);
    a = xv.z * wv.z; r.z = (a > 0.f) ? a : expm1f(a);
    a = xv.w * wv.w; r.w = (a > 0.f) ? a : expm1f(a);

    reinterpret_cast<float4*>(g_emb)[i] = r;
}

// ---------------------------------------------------------------------------
// Kernel 2: degree histogram of dst (int REDs, cheap).
// ---------------------------------------------------------------------------
__global__ void hist_kernel(const int* __restrict__ dst) {
    int i = blockIdx.x * blockDim.x + threadIdx.x;
    if (i < NUM_EDGES) atomicAdd(&g_deg[dst[i]], 1);
}

// ---------------------------------------------------------------------------
// Kernel 3a: per-block exclusive scan of degrees (256-wide chunks).
// Writes local-exclusive into g_off, block total into g_bsum.
// ---------------------------------------------------------------------------
__global__ void scan_local_kernel() {
    __shared__ int sh[256];
    const int t = threadIdx.x, b = blockIdx.x;
    const int i = b * 256 + t;
    int v = (i < NUM_NODES) ? g_deg[i] : 0;
    sh[t] = v;
    __syncthreads();
    #pragma unroll
    for (int ofs = 1; ofs < 256; ofs <<= 1) {
        int x = (t >= ofs) ? sh[t - ofs] : 0;
        __syncthreads();
        sh[t] += x;
        __syncthreads();
    }
    int incl = sh[t];
    if (i < NUM_NODES) g_off[i] = incl - v;        // local exclusive
    if (t == 255) g_bsum[b] = incl;                // block total
}

// ---------------------------------------------------------------------------
// Kernel 3b: add preceding-block totals; init cursors; finalize g_off[N].
// ---------------------------------------------------------------------------
__global__ void scan_add_kernel() {
    __shared__ int sb[256];
    const int t = threadIdx.x, b = blockIdx.x;
    const int i = b * 256 + t;
    int partial = 0;
    for (int j = t; j < b; j += 256) partial += g_bsum[j];
    sb[t] = partial;
    __syncthreads();
    #pragma unroll
    for (int s = 128; s > 0; s >>= 1) {
        if (t < s) sb[t] += sb[t + s];
        __syncthreads();
    }
    const int base = sb[0];
    if (i < NUM_NODES) {
        int o = g_off[i] + base;
        g_off[i]    = o;
        g_cursor[i] = o;
    }
    if (i == 0) g_off[NUM_NODES] = NUM_EDGES;      // total is a known constant
}

// ---------------------------------------------------------------------------
// Kernel 4: bucket edges by dst. packed = src | (flag<<16)  (src < 65536).
// ---------------------------------------------------------------------------
__global__ void fill_kernel(const int* __restrict__ e_feat,
                            const int* __restrict__ src,
                            const int* __restrict__ dst) {
    int i = blockIdx.x * blockDim.x + threadIdx.x;
    if (i >= NUM_EDGES) return;
    const int d = dst[i];
    const int e = e_feat[i];
    const int flag = (e >= 0 && e < 5) ? 1 : 0;
    const int pos = atomicAdd(&g_cursor[d], 1);
    g_packed[pos] = src[i] | (flag << 16);
}

// ---------------------------------------------------------------------------
// Kernel 5: per-node gather. One warp per node; lane l owns floats [4l,4l+4).
// Batch-load up to 32 edge records, shfl-broadcast, accumulate in registers,
// single float4 store (also initializes the poisoned output).
// ---------------------------------------------------------------------------
__global__ void gather_kernel(float* __restrict__ out) {
    const unsigned gtid = blockIdx.x * blockDim.x + threadIdx.x;
    const unsigned node = gtid >> 5;
    const unsigned lane = gtid & 31u;
    if (node >= NUM_NODES) return;

    const int start = g_off[node];
    const int end   = g_off[node + 1];
    const float4* __restrict__ emb4 = reinterpret_cast<const float4*>(g_emb);

    float4 acc = make_float4(0.f, 0.f, 0.f, 0.f);

    for (int base = start; base < end; base += 32) {
        const int idx = base + (int)lane;
        const int p   = (idx < end) ? g_packed[idx] : 0;
        const int cnt = min(32, end - base);
        for (int j = 0; j < cnt; j++) {
            const int pv = __shfl_sync(0xffffffffu, p, j);
            const int s  = pv & 0xFFFF;
            const float c = (pv & 0x10000) ? 2.0f : 1.0f;
            float4 v = emb4[(size_t)s * (DIM / 4) + lane];
            acc.x += v.x * c; acc.y += v.y * c;
            acc.z += v.z * c; acc.w += v.w * c;
        }
    }
    reinterpret_cast<float4*>(out)[(size_t)node * (DIM / 4) + lane] = acc;
}

// ---------------------------------------------------------------------------
// Launch chain: emb(+zero) -> hist -> scan -> scan_add -> fill -> gather.
// All graph-capturable; gather writes every output element (no memset needed).
// Inputs: graph_embedding f32, weight f32, e_feat i32, src i32, dst i32
// ---------------------------------------------------------------------------
extern "C" void kernel_launch(void* const* d_in, const int* in_sizes, int n_in,
                              void* d_out, int out_size) {
    const float* x  = (const float*)d_in[0];
    const float* w  = (const float*)d_in[1];
    const int*   ef = (const int*)d_in[2];
    const int*   sr = (const int*)d_in[3];
    const int*   ds = (const int*)d_in[4];
    float* out = (float*)d_out;

    const int total4 = NUM_NODES * DIM / 4;                 // 1,600,000
    emb_kernel<<<(total4 + 255) / 256, 256>>>(x, w);

    hist_kernel<<<(NUM_EDGES + 255) / 256, 256>>>(ds);
    scan_local_kernel<<<SCAN_BLOCKS, 256>>>();
    scan_add_kernel<<<SCAN_BLOCKS, 256>>>();
    fill_kernel<<<(NUM_EDGES + 255) / 256, 256>>>(ef, sr, ds);

    const long long threads = (long long)NUM_NODES * 32;    // 1.6M
    gather_kernel<<<(int)((threads + 255) / 256), 256>>>(out);
}